// round 11
// baseline (speedup 1.0000x reference)
#include <cuda_runtime.h>
#include <math.h>
#include <stdint.h>

// Problem dims
#define NW   2048
#define TW   32
#define NS   128
#define TS   16
#define NR   8
#define TR   16
#define EE   256
#define HH   256
#define G3   768
#define HSTR (2048*256)
#define VV   30000
#define PROWS 30080
#define PSTR ((size_t)PROWS * G3)

// persistent-chain tiling
#define CH_NT 32
#define CH_JT 32
#define SH_STRIDE 34
#define SH_BUF (16*SH_STRIDE)
#define CHAIN_SMEM ((256*3*CH_JT + 2*SH_BUF) * 4)

// ---------------- scratch (device globals; no runtime allocation) ----------------
__device__ float g_P[(size_t)2 * PROWS * G3];
__device__ float g_Gs[2*TS*NS*G3];
__device__ float g_Gr[2*TR*NR*G3];
__device__ float g_hA[2*HSTR];
__device__ float g_hB[2*HSTR];
__device__ float g_sent[NW*HH];
__device__ float g_rev[NS*HH];
__device__ float g_biz[NR*HH];
__device__ float g_WihT_w[2*256*G3];
__device__ float g_WhhT_w[2*256*G3];
__device__ float g_WihT_s[2*256*G3];
__device__ float g_WhhT_s[2*256*G3];
__device__ float g_WihT_r[2*256*G3];
__device__ float g_WhhT_r[2*256*G3];
__device__ int   g_tok32[NW*TW];
__device__ int   g_tok64;
__device__ unsigned g_bcount;
__device__ unsigned g_bphase;

// packed f32x2 FMA
__device__ __forceinline__ void ffma2(float2& d, float2 a, float2 b) {
    asm("fma.rn.f32x2 %0, %1, %2, %0;"
        : "+l"(reinterpret_cast<unsigned long long&>(d))
        : "l"(reinterpret_cast<unsigned long long&>(a)),
          "l"(reinterpret_cast<unsigned long long&>(b)));
}

// cp.async 16B
__device__ __forceinline__ void cp_async16(uint32_t saddr, const void* gptr) {
    asm volatile("cp.async.cg.shared.global [%0], [%1], 16;" :: "r"(saddr), "l"(gptr));
}
__device__ __forceinline__ void cp_commit() { asm volatile("cp.async.commit_group;"); }
__device__ __forceinline__ void cp_wait0()  { asm volatile("cp.async.wait_group 0;"); }

__device__ __forceinline__ float fsigmoid(float x) {
    return __fdividef(1.f, 1.f + __expf(-x));
}
__device__ __forceinline__ float ftanh(float x) {
    float e = __expf(2.f * x);
    return 1.f - __fdividef(2.f, e + 1.f);
}

// Grid-wide barrier for co-resident persistent grids.
// __threadfence (gpu scope) provides release/acquire AND L1 invalidation (CCTL.IVALL).
__device__ __forceinline__ void grid_bar(unsigned nb, unsigned ph0, unsigned tgt) {
    __syncthreads();
    if (threadIdx.x == 0) {
        __threadfence();
        unsigned old = atomicAdd(&g_bcount, 1);
        if (old == nb - 1) {
            atomicExch(&g_bcount, 0);
            __threadfence();
            atomicAdd(&g_bphase, 1);
        } else {
            while ((int)(*(volatile unsigned*)&g_bphase - ph0) < (int)tgt) { }
        }
        __threadfence();
    }
    __syncthreads();
}

// ---------------- tiny utility kernels ----------------
__global__ void add_dirs_k(const float* __restrict__ h, float* __restrict__ out, int count) {
    int i = blockIdx.x * 256 + threadIdx.x;
    if (i < count) out[i] = h[i] + h[HSTR + i];
}

__global__ void transpose6_k(
    const float* __restrict__ s0, const float* __restrict__ s1,
    const float* __restrict__ s2, const float* __restrict__ s3,
    const float* __restrict__ s4, const float* __restrict__ s5,
    float* __restrict__ d0, float* __restrict__ d1,
    float* __restrict__ d2, float* __restrict__ d3,
    float* __restrict__ d4, float* __restrict__ d5)
{
    __shared__ float tile[32][33];
    const float* srcs[6] = {s0, s1, s2, s3, s4, s5};
    float*       dsts[6] = {d0, d1, d2, d3, d4, d5};
    int w = blockIdx.z >> 1;
    int d = blockIdx.z & 1;
    const float* s = srcs[w] + (size_t)d * G3 * 256;
    float* o = dsts[w] + (size_t)d * 256 * G3;
    int r0 = blockIdx.x * 32;
    int c0 = blockIdx.y * 32;
    for (int i = threadIdx.y; i < 32; i += 8)
        tile[i][threadIdx.x] = s[(size_t)(r0 + i) * 256 + c0 + threadIdx.x];
    __syncthreads();
    for (int i = threadIdx.y; i < 32; i += 8)
        o[(size_t)(c0 + i) * G3 + r0 + threadIdx.x] = tile[threadIdx.x][i];
}

__global__ void detect_k(const int* __restrict__ t) {
    if (threadIdx.x == 0 && blockIdx.x == 0) {
        int is64 = 1;
        for (int i = 1; i < 256; i += 2)
            if (t[i] != 0) { is64 = 0; break; }
        g_tok64 = is64;
    }
}

__global__ void tok32_k(const void* __restrict__ tok) {
    int i = blockIdx.x * 256 + threadIdx.x;
    if (i < NW * TW)
        g_tok32[i] = g_tok64 ? (int)((const long long*)tok)[i]
                             : ((const int*)tok)[i];
}

// ---------------- vocab projection GEMM: P[d] = emb @ WihT[d] + bih[d] ----------------
__global__ __launch_bounds__(256, 2) void gemm_emb_k(
    const float* __restrict__ emb, const float* __restrict__ WT,
    const float* __restrict__ bih, float* __restrict__ P)
{
    __shared__ float sA[2][16][130];
    __shared__ float sB[2][16][128];
    int d  = blockIdx.z;
    int m0 = blockIdx.x * 128;
    int c0 = blockIdx.y * 128;
    int tid = threadIdx.x;
    int tx = tid & 15, ty = tid >> 4;
    const float* WTd = WT + (size_t)d * 256 * G3;

    int aRowLocal[2];
    const float* aSrc[2];
    int kqA = (tid & 3) << 2;
#pragma unroll
    for (int i = 0; i < 2; i++) {
        int row = i * 64 + (tid >> 2);
        aRowLocal[i] = row;
        int m = m0 + row;
        if (m > VV - 1) m = VV - 1;
        aSrc[i] = emb + (size_t)m * 256 + kqA;
    }
    int kkB = tid >> 5;
    int c4B = (tid & 31) << 2;
    const float* bSrc[2];
    uint32_t sBdst[2][2];
    {
        uint32_t sBbase = (uint32_t)__cvta_generic_to_shared(&sB[0][0][0]);
#pragma unroll
        for (int i = 0; i < 2; i++) {
            bSrc[i] = WTd + (size_t)(kkB + i * 8) * G3 + c0 + c4B;
#pragma unroll
            for (int b = 0; b < 2; b++)
                sBdst[b][i] = sBbase + (uint32_t)(b * 16 * 128 + (kkB + i * 8) * 128 + c4B) * 4u;
        }
    }

    float2 acc[4][8];
#pragma unroll
    for (int i = 0; i < 4; i++)
#pragma unroll
        for (int j = 0; j < 8; j++) acc[i][j] = make_float2(0.f, 0.f);

    float4 ra[2];
#pragma unroll
    for (int i = 0; i < 2; i++) cp_async16(sBdst[0][i], bSrc[i]);
    cp_commit();
#pragma unroll
    for (int i = 0; i < 2; i++) ra[i] = *(const float4*)(aSrc[i]);
#pragma unroll
    for (int i = 0; i < 2; i++) {
        sA[0][kqA + 0][aRowLocal[i]] = ra[i].x;
        sA[0][kqA + 1][aRowLocal[i]] = ra[i].y;
        sA[0][kqA + 2][aRowLocal[i]] = ra[i].z;
        sA[0][kqA + 3][aRowLocal[i]] = ra[i].w;
    }
    cp_wait0();
    __syncthreads();

    const int NKC = 256 / 16;
    for (int it = 0; it < NKC; it++) {
        int buf = it & 1;
        if (it + 1 < NKC) {
            int kc = (it + 1) * 16;
            int nb = buf ^ 1;
#pragma unroll
            for (int i = 0; i < 2; i++)
                cp_async16(sBdst[nb][i], bSrc[i] + (size_t)kc * G3);
            cp_commit();
#pragma unroll
            for (int i = 0; i < 2; i++) ra[i] = *(const float4*)(aSrc[i] + kc);
        }
#pragma unroll
        for (int kk = 0; kk < 16; kk++) {
            float2 ar[4];
            ar[0] = *(const float2*)&sA[buf][kk][ty * 4 + 0];
            ar[1] = *(const float2*)&sA[buf][kk][ty * 4 + 2];
            ar[2] = *(const float2*)&sA[buf][kk][64 + ty * 4 + 0];
            ar[3] = *(const float2*)&sA[buf][kk][64 + ty * 4 + 2];
            float4 b0 = *(const float4*)&sB[buf][kk][tx * 4];
            float4 b1 = *(const float4*)&sB[buf][kk][64 + tx * 4];
            float bs[8] = {b0.x, b0.y, b0.z, b0.w, b1.x, b1.y, b1.z, b1.w};
#pragma unroll
            for (int c = 0; c < 8; c++) {
                float2 bb = make_float2(bs[c], bs[c]);
#pragma unroll
                for (int rp = 0; rp < 4; rp++) ffma2(acc[rp][c], ar[rp], bb);
            }
        }
        if (it + 1 < NKC) {
            int nb = buf ^ 1;
#pragma unroll
            for (int i = 0; i < 2; i++) {
                sA[nb][kqA + 0][aRowLocal[i]] = ra[i].x;
                sA[nb][kqA + 1][aRowLocal[i]] = ra[i].y;
                sA[nb][kqA + 2][aRowLocal[i]] = ra[i].z;
                sA[nb][kqA + 3][aRowLocal[i]] = ra[i].w;
            }
            cp_wait0();
        }
        __syncthreads();
    }

    float* Pd = P + (size_t)d * PSTR;
    float4 bcl = *(const float4*)&bih[d * G3 + c0 + tx * 4];
    float4 bch = *(const float4*)&bih[d * G3 + c0 + 64 + tx * 4];
#pragma unroll
    for (int rp = 0; rp < 4; rp++) {
        int row = m0 + ((rp >> 1) << 6) + ty * 4 + ((rp & 1) << 1);
        float4 v;
        v = make_float4(acc[rp][0].x + bcl.x, acc[rp][1].x + bcl.y,
                        acc[rp][2].x + bcl.z, acc[rp][3].x + bcl.w);
        *(float4*)&Pd[(size_t)row * G3 + c0 + tx * 4] = v;
        v = make_float4(acc[rp][0].y + bcl.x, acc[rp][1].y + bcl.y,
                        acc[rp][2].y + bcl.z, acc[rp][3].y + bcl.w);
        *(float4*)&Pd[(size_t)(row + 1) * G3 + c0 + tx * 4] = v;
        v = make_float4(acc[rp][4].x + bch.x, acc[rp][5].x + bch.y,
                        acc[rp][6].x + bch.z, acc[rp][7].x + bch.w);
        *(float4*)&Pd[(size_t)row * G3 + c0 + 64 + tx * 4] = v;
        v = make_float4(acc[rp][4].y + bch.x, acc[rp][5].y + bch.y,
                        acc[rp][6].y + bch.z, acc[rp][7].y + bch.w);
        *(float4*)&Pd[(size_t)(row + 1) * G3 + c0 + 64 + tx * 4] = v;
    }
}

// ---------------- input-projection GEMM (dense; sentence/review levels) ----------------
__global__ __launch_bounds__(256, 2) void gemm_in_k(
    const float* __restrict__ A, const float* __restrict__ WT,
    const float* __restrict__ bih, float* __restrict__ G, int N, int T)
{
    __shared__ float sA[2][16][130];
    __shared__ float sB[2][16][128];
    int d  = blockIdx.z;
    int m0 = blockIdx.x * 128;
    int c0 = blockIdx.y * 128;
    int tid = threadIdx.x;
    int tx = tid & 15, ty = tid >> 4;
    const float* WTd = WT + (size_t)d * 256 * G3;

    int aRowLocal[2];
    const float* aSrc[2];
    int kqA = (tid & 3) << 2;
#pragma unroll
    for (int i = 0; i < 2; i++) {
        int row = i * 64 + (tid >> 2);
        aRowLocal[i] = row;
        int m = m0 + row;
        int t = m / N;
        int n = m - t * N;
        int tt = d ? (T - 1 - t) : t;
        aSrc[i] = A + (size_t)(n * T + tt) * 256 + kqA;
    }
    int kkB = tid >> 5;
    int c4B = (tid & 31) << 2;
    const float* bSrc[2];
    uint32_t sBdst[2][2];
    {
        uint32_t sBbase = (uint32_t)__cvta_generic_to_shared(&sB[0][0][0]);
#pragma unroll
        for (int i = 0; i < 2; i++) {
            bSrc[i] = WTd + (size_t)(kkB + i * 8) * G3 + c0 + c4B;
#pragma unroll
            for (int b = 0; b < 2; b++)
                sBdst[b][i] = sBbase + (uint32_t)(b * 16 * 128 + (kkB + i * 8) * 128 + c4B) * 4u;
        }
    }

    float2 acc[4][8];
#pragma unroll
    for (int i = 0; i < 4; i++)
#pragma unroll
        for (int j = 0; j < 8; j++) acc[i][j] = make_float2(0.f, 0.f);

    float4 ra[2];
#pragma unroll
    for (int i = 0; i < 2; i++) cp_async16(sBdst[0][i], bSrc[i]);
    cp_commit();
#pragma unroll
    for (int i = 0; i < 2; i++) ra[i] = *(const float4*)(aSrc[i]);
#pragma unroll
    for (int i = 0; i < 2; i++) {
        sA[0][kqA + 0][aRowLocal[i]] = ra[i].x;
        sA[0][kqA + 1][aRowLocal[i]] = ra[i].y;
        sA[0][kqA + 2][aRowLocal[i]] = ra[i].z;
        sA[0][kqA + 3][aRowLocal[i]] = ra[i].w;
    }
    cp_wait0();
    __syncthreads();

    const int NKC = 256 / 16;
    for (int it = 0; it < NKC; it++) {
        int buf = it & 1;
        if (it + 1 < NKC) {
            int kc = (it + 1) * 16;
            int nb = buf ^ 1;
#pragma unroll
            for (int i = 0; i < 2; i++)
                cp_async16(sBdst[nb][i], bSrc[i] + (size_t)kc * G3);
            cp_commit();
#pragma unroll
            for (int i = 0; i < 2; i++) ra[i] = *(const float4*)(aSrc[i] + kc);
        }
#pragma unroll
        for (int kk = 0; kk < 16; kk++) {
            float2 ar[4];
            ar[0] = *(const float2*)&sA[buf][kk][ty * 4 + 0];
            ar[1] = *(const float2*)&sA[buf][kk][ty * 4 + 2];
            ar[2] = *(const float2*)&sA[buf][kk][64 + ty * 4 + 0];
            ar[3] = *(const float2*)&sA[buf][kk][64 + ty * 4 + 2];
            float4 b0 = *(const float4*)&sB[buf][kk][tx * 4];
            float4 b1 = *(const float4*)&sB[buf][kk][64 + tx * 4];
            float bs[8] = {b0.x, b0.y, b0.z, b0.w, b1.x, b1.y, b1.z, b1.w};
#pragma unroll
            for (int c = 0; c < 8; c++) {
                float2 bb = make_float2(bs[c], bs[c]);
#pragma unroll
                for (int rp = 0; rp < 4; rp++) ffma2(acc[rp][c], ar[rp], bb);
            }
        }
        if (it + 1 < NKC) {
            int nb = buf ^ 1;
#pragma unroll
            for (int i = 0; i < 2; i++) {
                sA[nb][kqA + 0][aRowLocal[i]] = ra[i].x;
                sA[nb][kqA + 1][aRowLocal[i]] = ra[i].y;
                sA[nb][kqA + 2][aRowLocal[i]] = ra[i].z;
                sA[nb][kqA + 3][aRowLocal[i]] = ra[i].w;
            }
            cp_wait0();
        }
        __syncthreads();
    }

    float* Gd = G + (size_t)d * N * T * G3;
    float4 bcl = *(const float4*)&bih[d * G3 + c0 + tx * 4];
    float4 bch = *(const float4*)&bih[d * G3 + c0 + 64 + tx * 4];
#pragma unroll
    for (int rp = 0; rp < 4; rp++) {
        int row = m0 + ((rp >> 1) << 6) + ty * 4 + ((rp & 1) << 1);
        float4 v;
        v = make_float4(acc[rp][0].x + bcl.x, acc[rp][1].x + bcl.y,
                        acc[rp][2].x + bcl.z, acc[rp][3].x + bcl.w);
        *(float4*)&Gd[(size_t)row * G3 + c0 + tx * 4] = v;
        v = make_float4(acc[rp][0].y + bcl.x, acc[rp][1].y + bcl.y,
                        acc[rp][2].y + bcl.z, acc[rp][3].y + bcl.w);
        *(float4*)&Gd[(size_t)(row + 1) * G3 + c0 + tx * 4] = v;
        v = make_float4(acc[rp][4].x + bch.x, acc[rp][5].x + bch.y,
                        acc[rp][6].x + bch.z, acc[rp][7].x + bch.w);
        *(float4*)&Gd[(size_t)row * G3 + c0 + 64 + tx * 4] = v;
        v = make_float4(acc[rp][4].y + bch.x, acc[rp][5].y + bch.y,
                        acc[rp][6].y + bch.z, acc[rp][7].y + bch.w);
        *(float4*)&Gd[(size_t)(row + 1) * G3 + c0 + 64 + tx * 4] = v;
    }
}

// ---------------- GRU step 0 (word level; gathered from P) ----------------
__global__ void gru_step0_k(float* __restrict__ hn, const float* __restrict__ bhh,
                            const float* __restrict__ Gt, size_t dG, int N,
                            const int* __restrict__ tok32, int T)
{
    int i = blockIdx.x * 256 + threadIdx.x;
    int total = 2 * N * 256;
    if (i >= total) return;
    int d = i / (N * 256);
    int rem = i - d * (N * 256);
    int n = rem >> 8;
    int j = rem & 255;
    const float* Gd = Gt + (size_t)d * dG;
    const float* bh = bhh + d * G3;
    size_t gb;
    if (tok32) {
        int tt = d ? (T - 1) : 0;
        int tv = tok32[n * T + tt];
        gb = (size_t)tv * G3 + j;
    } else {
        gb = (size_t)n * G3 + j;
    }
    float r  = fsigmoid(Gd[gb] + bh[j]);
    float z  = fsigmoid(Gd[gb + 256] + bh[256 + j]);
    float nn = ftanh(Gd[gb + 512] + r * bh[512 + j]);
    hn[(size_t)d * HSTR + (size_t)n * 256 + j] = (1.f - z) * nn;
}

// ---------------- fused GRU recurrent step (word level) ----------------
template<int JT, bool TOK>
__global__ __launch_bounds__(256, 2) void gru_step_k(
    const float* __restrict__ hp, float* __restrict__ hn,
    const float* __restrict__ WhhT, const float* __restrict__ bhh,
    const float* __restrict__ Gt, size_t dG, int N,
    const int* __restrict__ tok32, int t, int T)
{
    __shared__ float sH[2][16][66];
    __shared__ float sW[2][16 * 3 * JT];
    int d  = blockIdx.z;
    int n0 = blockIdx.x * 64;
    int j0 = blockIdx.y * JT;
    int tid = threadIdx.x;
    const int TXN = JT / 2;
    const int TYN = 256 / TXN;
    const int NPT = 64 / TYN;
    int tx = tid % TXN, ty = tid / TXN;
    const float* hpd = hp + (size_t)d * HSTR;
    const float* Wd  = WhhT + (size_t)d * 256 * G3;

    int hRow = tid >> 2;
    int hKq  = (tid & 3) << 2;
    bool hValid = (n0 + hRow) < N;
    const float* hSrc = hpd + (size_t)(hValid ? (n0 + hRow) : 0) * 256 + hKq;
    const int NF4 = 16 * 3 * JT / 4;
    const int NP4 = (NF4 + 255) / 256;
    const float* wSrc[NP4];
    uint32_t wDstB[2][NP4];
    bool wAct[NP4];
    {
        uint32_t sWbase = (uint32_t)__cvta_generic_to_shared(&sW[0][0]);
#pragma unroll
        for (int i = 0; i < NP4; i++) {
            int idx = i * 256 + tid;
            wAct[i] = idx < NF4;
            int perk = 3 * JT / 4;
            int ii = wAct[i] ? idx : 0;
            int kk = ii / perk;
            int r = ii - kk * perk;
            int g = r / (JT / 4);
            int j4 = (r - g * (JT / 4)) << 2;
            wSrc[i] = Wd + (size_t)kk * G3 + g * 256 + j0 + j4;
            int fofs = kk * (3 * JT) + g * JT + j4;
#pragma unroll
            for (int b = 0; b < 2; b++)
                wDstB[b][i] = sWbase + (uint32_t)(b * 16 * 3 * JT + fofs) * 4u;
        }
    }

    float2 acc[NPT/2][3][2];
#pragma unroll
    for (int a = 0; a < NPT/2; a++)
#pragma unroll
        for (int g = 0; g < 3; g++)
#pragma unroll
            for (int jj = 0; jj < 2; jj++) acc[a][g][jj] = make_float2(0.f, 0.f);

    float4 rh;
#pragma unroll
    for (int i = 0; i < NP4; i++)
        if (wAct[i]) cp_async16(wDstB[0][i], wSrc[i]);
    cp_commit();
    rh = hValid ? *(const float4*)(hSrc) : make_float4(0.f, 0.f, 0.f, 0.f);
    sH[0][hKq + 0][hRow] = rh.x; sH[0][hKq + 1][hRow] = rh.y;
    sH[0][hKq + 2][hRow] = rh.z; sH[0][hKq + 3][hRow] = rh.w;
    cp_wait0();
    __syncthreads();

    const int NKC = 256 / 16;
    for (int it = 0; it < NKC; it++) {
        int buf = it & 1;
        if (it + 1 < NKC) {
            int kc = (it + 1) * 16;
            int nb = buf ^ 1;
#pragma unroll
            for (int i = 0; i < NP4; i++)
                if (wAct[i]) cp_async16(wDstB[nb][i], wSrc[i] + (size_t)kc * G3);
            cp_commit();
            rh = hValid ? *(const float4*)(hSrc + kc) : make_float4(0.f, 0.f, 0.f, 0.f);
        }
#pragma unroll
        for (int kk = 0; kk < 16; kk++) {
            float2 ar[NPT/2];
#pragma unroll
            for (int rp = 0; rp < NPT/2; rp++)
                ar[rp] = *(const float2*)&sH[buf][kk][ty * NPT + rp * 2];
#pragma unroll
            for (int g = 0; g < 3; g++) {
                float2 w = *(const float2*)&sW[buf][kk * (3 * JT) + g * JT + tx * 2];
                float2 b0 = make_float2(w.x, w.x);
                float2 b1 = make_float2(w.y, w.y);
#pragma unroll
                for (int rp = 0; rp < NPT/2; rp++) {
                    ffma2(acc[rp][g][0], ar[rp], b0);
                    ffma2(acc[rp][g][1], ar[rp], b1);
                }
            }
        }
        if (it + 1 < NKC) {
            int nb = buf ^ 1;
            sH[nb][hKq + 0][hRow] = rh.x; sH[nb][hKq + 1][hRow] = rh.y;
            sH[nb][hKq + 2][hRow] = rh.z; sH[nb][hKq + 3][hRow] = rh.w;
            cp_wait0();
        }
        __syncthreads();
    }

    const float* Gd = Gt + (size_t)d * dG;
    const float* bh = bhh + d * G3;
    float* hnd = hn + (size_t)d * HSTR;
    int jb = j0 + tx * 2;
    int tt = d ? (T - 1 - t) : t;
    float2 bh0 = *(const float2*)&bh[jb];
    float2 bh1 = *(const float2*)&bh[256 + jb];
    float2 bh2 = *(const float2*)&bh[512 + jb];
#pragma unroll
    for (int rp = 0; rp < NPT/2; rp++) {
#pragma unroll
        for (int lane = 0; lane < 2; lane++) {
            int n = n0 + ty * NPT + rp * 2 + lane;
            if (n >= N) continue;
            size_t gb;
            if (TOK) {
                int tv = tok32[n * T + tt];
                gb = (size_t)tv * G3 + jb;
            } else {
                gb = (size_t)n * G3 + jb;
            }
            float2 G0 = *(const float2*)&Gd[gb];
            float2 G1 = *(const float2*)&Gd[gb + 256];
            float2 G2 = *(const float2*)&Gd[gb + 512];
            float2 hp2 = *(const float2*)&hpd[(size_t)n * 256 + jb];
            float2 res;
#pragma unroll
            for (int jj = 0; jj < 2; jj++) {
                float a0 = lane ? acc[rp][0][jj].y : acc[rp][0][jj].x;
                float a1 = lane ? acc[rp][1][jj].y : acc[rp][1][jj].x;
                float a2 = lane ? acc[rp][2][jj].y : acc[rp][2][jj].x;
                float gx0 = jj ? G0.y : G0.x, gx1 = jj ? G1.y : G1.x, gx2 = jj ? G2.y : G2.x;
                float bb0 = jj ? bh0.y : bh0.x, bb1 = jj ? bh1.y : bh1.x, bb2 = jj ? bh2.y : bh2.x;
                float hpv = jj ? hp2.y : hp2.x;
                float r  = fsigmoid(gx0 + a0 + bb0);
                float z  = fsigmoid(gx1 + a1 + bb1);
                float nn = ftanh(gx2 + r * (a2 + bb2));
                float o  = (1.f - z) * nn + z * hpv;
                if (jj) res.y = o; else res.x = o;
            }
            *(float2*)&hnd[(size_t)n * 256 + jb] = res;
        }
    }
}

// ---------------- persistent GRU chain (sentence/review levels) ----------------
// One launch runs all T steps. Whh block-tile cached in smem for the whole chain.
// Grid: (ceil(N/32), 8, 2); co-residency guaranteed (<=148 blocks).
__global__ __launch_bounds__(256) void gru_chain_k(
    float* bufA, float* bufB,
    const float* __restrict__ WhhT, const float* __restrict__ bhh,
    const float* __restrict__ Gbase, size_t dG, int N, int T,
    float* __restrict__ outSum, unsigned nb)
{
    extern __shared__ float sm[];
    float* sW = sm;                        // [256][3][CH_JT]
    float* sH = sm + 256 * 3 * CH_JT;      // [2][16][SH_STRIDE]

    unsigned ph0 = *(volatile unsigned*)&g_bphase;

    int tid = threadIdx.x;
    int d  = blockIdx.z;
    int n0 = blockIdx.x * CH_NT;
    int j0 = blockIdx.y * CH_JT;
    const float* Wd = WhhT + (size_t)d * 256 * G3;
    const float* bh = bhh + d * G3;

    // Load W tile once (96 KB): 6144 float4s, 24 per thread.
    {
        uint32_t sWb = (uint32_t)__cvta_generic_to_shared(sW);
#pragma unroll
        for (int p = 0; p < 24; p++) {
            int idx = p * 256 + tid;
            int kkg = idx / 24;
            int r = idx - kkg * 24;
            int g = r >> 3;
            int j4 = (r & 7) << 2;
            cp_async16(sWb + (uint32_t)(kkg * 96 + g * 32 + j4) * 4u,
                       Wd + (size_t)kkg * G3 + g * 256 + j0 + j4);
        }
        cp_commit();
        cp_wait0();
    }
    __syncthreads();

    // step 0: h==0 -> elementwise, write bufB (index 1)
    {
        const float* Gd = Gbase + (size_t)d * dG;
        float* h1 = bufB + (size_t)d * HSTR;
#pragma unroll
        for (int p = 0; p < 4; p++) {
            int idx = p * 256 + tid;
            int n = n0 + (idx >> 5);
            int j = j0 + (idx & 31);
            if (n < N) {
                size_t gb = (size_t)n * G3 + j;
                float r  = fsigmoid(Gd[gb] + bh[j]);
                float z  = fsigmoid(Gd[gb + 256] + bh[256 + j]);
                float nn = ftanh(Gd[gb + 512] + r * bh[512 + j]);
                h1[(size_t)n * 256 + j] = (1.f - z) * nn;
            }
        }
    }
    grid_bar(nb, ph0, 1);

    int tx = tid & 15, ty = tid >> 4;      // tx: j pairs, ty: n pairs
    int hRow = tid >> 3;                   // 0..31
    int hK2 = (tid & 7) << 1;              // 0,2,..,14
    bool hValid = (n0 + hRow) < N;
    int jb = j0 + tx * 2;
    float2 bh0 = *(const float2*)&bh[jb];
    float2 bh1 = *(const float2*)&bh[256 + jb];
    float2 bh2 = *(const float2*)&bh[512 + jb];
    float* bufs[2] = {bufA, bufB};

    for (int t = 1; t < T; t++) {
        const float* hp = bufs[t & 1] + (size_t)d * HSTR;
        float* hn = bufs[(t & 1) ^ 1] + (size_t)d * HSTR;
        const float* Gd = Gbase + (size_t)d * dG + (size_t)t * N * G3;
        const float* hSrc = hp + (size_t)(hValid ? (n0 + hRow) : 0) * 256 + hK2;

        float2 acc[3][2];
#pragma unroll
        for (int g = 0; g < 3; g++)
#pragma unroll
            for (int jj = 0; jj < 2; jj++) acc[g][jj] = make_float2(0.f, 0.f);

        float2 rh = hValid ? *(const float2*)hSrc : make_float2(0.f, 0.f);
        sH[0 * SH_BUF + (hK2 + 0) * SH_STRIDE + hRow] = rh.x;
        sH[0 * SH_BUF + (hK2 + 1) * SH_STRIDE + hRow] = rh.y;
        __syncthreads();

        for (int it = 0; it < 16; it++) {
            int buf = it & 1;
            if (it + 1 < 16)
                rh = hValid ? *(const float2*)(hSrc + (it + 1) * 16)
                            : make_float2(0.f, 0.f);
#pragma unroll
            for (int kk = 0; kk < 16; kk++) {
                float2 ar = *(const float2*)&sH[buf * SH_BUF + kk * SH_STRIDE + ty * 2];
                int wbase = (it * 16 + kk) * 96;
#pragma unroll
                for (int g = 0; g < 3; g++) {
                    float2 w = *(const float2*)&sW[wbase + g * 32 + tx * 2];
                    ffma2(acc[g][0], ar, make_float2(w.x, w.x));
                    ffma2(acc[g][1], ar, make_float2(w.y, w.y));
                }
            }
            if (it + 1 < 16) {
                int nbuf = buf ^ 1;
                sH[nbuf * SH_BUF + (hK2 + 0) * SH_STRIDE + hRow] = rh.x;
                sH[nbuf * SH_BUF + (hK2 + 1) * SH_STRIDE + hRow] = rh.y;
            }
            __syncthreads();
        }

#pragma unroll
        for (int lane = 0; lane < 2; lane++) {
            int n = n0 + ty * 2 + lane;
            if (n >= N) continue;
            size_t gb = (size_t)n * G3 + jb;
            float2 G0 = *(const float2*)&Gd[gb];
            float2 G1 = *(const float2*)&Gd[gb + 256];
            float2 G2 = *(const float2*)&Gd[gb + 512];
            float2 hp2 = *(const float2*)&hp[(size_t)n * 256 + jb];
            float2 res;
#pragma unroll
            for (int jj = 0; jj < 2; jj++) {
                float a0 = lane ? acc[0][jj].y : acc[0][jj].x;
                float a1 = lane ? acc[1][jj].y : acc[1][jj].x;
                float a2 = lane ? acc[2][jj].y : acc[2][jj].x;
                float gx0 = jj ? G0.y : G0.x, gx1 = jj ? G1.y : G1.x, gx2 = jj ? G2.y : G2.x;
                float bb0 = jj ? bh0.y : bh0.x, bb1 = jj ? bh1.y : bh1.x, bb2 = jj ? bh2.y : bh2.x;
                float hpv = jj ? hp2.y : hp2.x;
                float r  = fsigmoid(gx0 + a0 + bb0);
                float z  = fsigmoid(gx1 + a1 + bb1);
                float nn = ftanh(gx2 + r * (a2 + bb2));
                float o  = (1.f - z) * nn + z * hpv;
                if (jj) res.y = o; else res.x = o;
            }
            *(float2*)&hn[(size_t)n * 256 + jb] = res;
        }
        grid_bar(nb, ph0, (unsigned)(t + 1));
    }

    // fold add_dirs: d==0 blocks write fwd+bwd sum for their tile
    if (d == 0) {
        int fb = ((T - 1) & 1) ^ 1;
        const float* fin = bufs[fb];
#pragma unroll
        for (int p = 0; p < 4; p++) {
            int idx = p * 256 + tid;
            int n = n0 + (idx >> 5);
            int j = j0 + (idx & 31);
            if (n < N)
                outSum[(size_t)n * HH + j] =
                    fin[(size_t)n * 256 + j] + fin[HSTR + (size_t)n * 256 + j];
        }
    }
}

// ---------------- FC head: Linear(256->128) -> SELU -> Linear(128->1) ----------------
__global__ void fc_head_k(const float* __restrict__ in, const float* __restrict__ W1,
                          const float* __restrict__ b1, const float* __restrict__ W2,
                          const float* __restrict__ b2, float* __restrict__ out)
{
    __shared__ float red[128];
    int row = blockIdx.x, j = threadIdx.x;
    const float* x = in + (size_t)row * 256;
    const float* w = W1 + (size_t)j * 256;
    float s = b1[j];
#pragma unroll 4
    for (int k = 0; k < 256; k += 4) {
        float4 xv = *(const float4*)&x[k];
        float4 wv = *(const float4*)&w[k];
        s += xv.x * wv.x + xv.y * wv.y + xv.z * wv.z + xv.w * wv.w;
    }
    const float SC = 1.0507009873554805f, AL = 1.6732632423543772f;
    float v = s > 0.f ? SC * s : SC * AL * (expf(s) - 1.f);
    red[j] = v * W2[j];
    __syncthreads();
    for (int o = 64; o > 0; o >>= 1) {
        if (j < o) red[j] += red[j + o];
        __syncthreads();
    }
    if (j == 0) out[row] = red[0] + b2[0];
}

// ---------------- orchestration ----------------
extern "C" void kernel_launch(void* const* d_in, const int* in_sizes, int n_in,
                              void* d_out, int out_size)
{
    const void*  tok   = d_in[0];
    const float* emb   = (const float*)d_in[1];
    const float* wWih  = (const float*)d_in[2];
    const float* wWhh  = (const float*)d_in[3];
    const float* wbih  = (const float*)d_in[4];
    const float* wbhh  = (const float*)d_in[5];
    const float* sWih  = (const float*)d_in[6];
    const float* sWhh  = (const float*)d_in[7];
    const float* sbih  = (const float*)d_in[8];
    const float* sbhh  = (const float*)d_in[9];
    const float* rWih  = (const float*)d_in[10];
    const float* rWhh  = (const float*)d_in[11];
    const float* rbih  = (const float*)d_in[12];
    const float* rbhh  = (const float*)d_in[13];
    const float* rfcW1 = (const float*)d_in[14];
    const float* rfcb1 = (const float*)d_in[15];
    const float* rfcW2 = (const float*)d_in[16];
    const float* rfcb2 = (const float*)d_in[17];
    const float* pfcW1 = (const float*)d_in[18];
    const float* pfcb1 = (const float*)d_in[19];
    const float* pfcW2 = (const float*)d_in[20];
    const float* pfcb2 = (const float*)d_in[21];
    float* out = (float*)d_out;

    dim3 tb(32, 8);
    float *pWihT_w, *pWhhT_w, *pWihT_s, *pWhhT_s, *pWihT_r, *pWhhT_r;
    float *pP, *pGs, *pGr, *pHA, *pHB, *pSent, *pRev, *pBiz;
    int *pTok32;
    cudaGetSymbolAddress((void**)&pWihT_w, g_WihT_w);
    cudaGetSymbolAddress((void**)&pWhhT_w, g_WhhT_w);
    cudaGetSymbolAddress((void**)&pWihT_s, g_WihT_s);
    cudaGetSymbolAddress((void**)&pWhhT_s, g_WhhT_s);
    cudaGetSymbolAddress((void**)&pWihT_r, g_WihT_r);
    cudaGetSymbolAddress((void**)&pWhhT_r, g_WhhT_r);
    cudaGetSymbolAddress((void**)&pP,   g_P);
    cudaGetSymbolAddress((void**)&pGs,  g_Gs);
    cudaGetSymbolAddress((void**)&pGr,  g_Gr);
    cudaGetSymbolAddress((void**)&pHA,  g_hA);
    cudaGetSymbolAddress((void**)&pHB,  g_hB);
    cudaGetSymbolAddress((void**)&pSent, g_sent);
    cudaGetSymbolAddress((void**)&pRev,  g_rev);
    cudaGetSymbolAddress((void**)&pBiz,  g_biz);
    cudaGetSymbolAddress((void**)&pTok32, g_tok32);

    cudaFuncSetAttribute(gru_chain_k,
                         cudaFuncAttributeMaxDynamicSharedMemorySize, CHAIN_SMEM);

    transpose6_k<<<dim3(24, 8, 12), tb>>>(
        wWih, wWhh, sWih, sWhh, rWih, rWhh,
        pWihT_w, pWhhT_w, pWihT_s, pWhhT_s, pWihT_r, pWhhT_r);

    detect_k<<<1, 32>>>((const int*)tok);
    tok32_k<<<(NW * TW + 255) / 256, 256>>>(tok);

    // ---- word level: project vocab table once, gather per step ----
    gemm_emb_k<<<dim3(PROWS / 128, 6, 2), 256>>>(emb, pWihT_w, wbih, pP);
    {
        float* ha = pHA; float* hb = pHB;
        gru_step0_k<<<(2 * NW * 256 + 255) / 256, 256>>>(hb, wbhh,
            pP, PSTR, NW, pTok32, TW);
        { float* tmp = ha; ha = hb; hb = tmp; }
        for (int t = 1; t < TW; t++) {
            gru_step_k<64, true><<<dim3(32, 4, 2), 256>>>(ha, hb, pWhhT_w, wbhh,
                pP, PSTR, NW, pTok32, t, TW);
            float* tmp = ha; ha = hb; hb = tmp;
        }
        add_dirs_k<<<2048, 256>>>(ha, pSent, NW * HH);
    }

    // ---- sentence level: persistent chain (64 blocks) ----
    gemm_in_k<<<dim3(16, 6, 2), 256>>>(pSent, pWihT_s, sbih, pGs, NS, TS);
    gru_chain_k<<<dim3(4, 8, 2), 256, CHAIN_SMEM>>>(
        pHA, pHB, pWhhT_s, sbhh, pGs, (size_t)TS * NS * G3, NS, TS, pRev, 64u);

    fc_head_k<<<128, 128>>>(pRev, rfcW1, rfcb1, rfcW2, rfcb2, out + 8);

    // ---- review level: persistent chain (16 blocks) ----
    gemm_in_k<<<dim3(1, 6, 2), 256>>>(pRev, pWihT_r, rbih, pGr, NR, TR);
    gru_chain_k<<<dim3(1, 8, 2), 256, CHAIN_SMEM>>>(
        pHA, pHB, pWhhT_r, rbhh, pGr, (size_t)TR * NR * G3, NR, TR, pBiz, 16u);

    fc_head_k<<<8, 128>>>(pBiz, pfcW1, pfcb1, pfcW2, pfcb2, out);
}

// round 13
// speedup vs baseline: 1.0718x; 1.0718x over previous
#include <cuda_runtime.h>
#include <math.h>
#include <stdint.h>

// Problem dims
#define NW   2048
#define TW   32
#define NS   128
#define TS   16
#define NR   8
#define TR   16
#define EE   256
#define HH   256
#define G3   768
#define HSTR (2048*256)
#define VV   30000
#define PROWS 30080
#define PSTR ((size_t)PROWS * G3)

// ---------------- scratch (device globals; no runtime allocation) ----------------
__device__ float g_P[(size_t)2 * PROWS * G3];
__device__ float g_Gs[2*TS*NS*G3];
__device__ float g_Gr[2*TR*NR*G3];
__device__ float g_hA[2*HSTR];
__device__ float g_hB[2*HSTR];
__device__ float g_sent[NW*HH];
__device__ float g_rev[NS*HH];
__device__ float g_biz[NR*HH];
__device__ float g_WihT_w[2*256*G3];
__device__ float g_WhhT_w[2*256*G3];
__device__ float g_WihT_s[2*256*G3];
__device__ float g_WhhT_s[2*256*G3];
__device__ float g_WihT_r[2*256*G3];
__device__ float g_WhhT_r[2*256*G3];
__device__ int   g_tok32[NW*TW];
__device__ int   g_tok64;

// packed f32x2 FMA
__device__ __forceinline__ void ffma2(float2& d, float2 a, float2 b) {
    asm("fma.rn.f32x2 %0, %1, %2, %0;"
        : "+l"(reinterpret_cast<unsigned long long&>(d))
        : "l"(reinterpret_cast<unsigned long long&>(a)),
          "l"(reinterpret_cast<unsigned long long&>(b)));
}

// cp.async 16B
__device__ __forceinline__ void cp_async16(uint32_t saddr, const void* gptr) {
    asm volatile("cp.async.cg.shared.global [%0], [%1], 16;" :: "r"(saddr), "l"(gptr));
}
__device__ __forceinline__ void cp_commit() { asm volatile("cp.async.commit_group;"); }
__device__ __forceinline__ void cp_wait0()  { asm volatile("cp.async.wait_group 0;"); }

__device__ __forceinline__ float fsigmoid(float x) {
    return __fdividef(1.f, 1.f + __expf(-x));
}
__device__ __forceinline__ float ftanh(float x) {
    float e = __expf(2.f * x);
    return 1.f - __fdividef(2.f, e + 1.f);
}

// ---------------- tiny utility kernels ----------------
__global__ void add_dirs_k(const float* __restrict__ h, float* __restrict__ out, int count) {
    int i = blockIdx.x * 256 + threadIdx.x;
    if (i < count) out[i] = h[i] + h[HSTR + i];
}

__global__ void transpose6_k(
    const float* __restrict__ s0, const float* __restrict__ s1,
    const float* __restrict__ s2, const float* __restrict__ s3,
    const float* __restrict__ s4, const float* __restrict__ s5,
    float* __restrict__ d0, float* __restrict__ d1,
    float* __restrict__ d2, float* __restrict__ d3,
    float* __restrict__ d4, float* __restrict__ d5)
{
    __shared__ float tile[32][33];
    const float* srcs[6] = {s0, s1, s2, s3, s4, s5};
    float*       dsts[6] = {d0, d1, d2, d3, d4, d5};
    int w = blockIdx.z >> 1;
    int d = blockIdx.z & 1;
    const float* s = srcs[w] + (size_t)d * G3 * 256;
    float* o = dsts[w] + (size_t)d * 256 * G3;
    int r0 = blockIdx.x * 32;
    int c0 = blockIdx.y * 32;
    for (int i = threadIdx.y; i < 32; i += 8)
        tile[i][threadIdx.x] = s[(size_t)(r0 + i) * 256 + c0 + threadIdx.x];
    __syncthreads();
    for (int i = threadIdx.y; i < 32; i += 8)
        o[(size_t)(c0 + i) * G3 + r0 + threadIdx.x] = tile[threadIdx.x][i];
}

__global__ void detect_k(const int* __restrict__ t) {
    if (threadIdx.x == 0 && blockIdx.x == 0) {
        int is64 = 1;
        for (int i = 1; i < 256; i += 2)
            if (t[i] != 0) { is64 = 0; break; }
        g_tok64 = is64;
    }
}

__global__ void tok32_k(const void* __restrict__ tok) {
    int i = blockIdx.x * 256 + threadIdx.x;
    if (i < NW * TW)
        g_tok32[i] = g_tok64 ? (int)((const long long*)tok)[i]
                             : ((const int*)tok)[i];
}

// ---------------- vocab projection GEMM: P[d] = emb @ WihT[d] + bih[d] ----------------
__global__ __launch_bounds__(256, 2) void gemm_emb_k(
    const float* __restrict__ emb, const float* __restrict__ WT,
    const float* __restrict__ bih, float* __restrict__ P)
{
    __shared__ float sA[2][16][130];
    __shared__ float sB[2][16][128];
    int d  = blockIdx.z;
    int m0 = blockIdx.x * 128;
    int c0 = blockIdx.y * 128;
    int tid = threadIdx.x;
    int tx = tid & 15, ty = tid >> 4;
    const float* WTd = WT + (size_t)d * 256 * G3;

    int aRowLocal[2];
    const float* aSrc[2];
    int kqA = (tid & 3) << 2;
#pragma unroll
    for (int i = 0; i < 2; i++) {
        int row = i * 64 + (tid >> 2);
        aRowLocal[i] = row;
        int m = m0 + row;
        if (m > VV - 1) m = VV - 1;
        aSrc[i] = emb + (size_t)m * 256 + kqA;
    }
    int kkB = tid >> 5;
    int c4B = (tid & 31) << 2;
    const float* bSrc[2];
    uint32_t sBdst[2][2];
    {
        uint32_t sBbase = (uint32_t)__cvta_generic_to_shared(&sB[0][0][0]);
#pragma unroll
        for (int i = 0; i < 2; i++) {
            bSrc[i] = WTd + (size_t)(kkB + i * 8) * G3 + c0 + c4B;
#pragma unroll
            for (int b = 0; b < 2; b++)
                sBdst[b][i] = sBbase + (uint32_t)(b * 16 * 128 + (kkB + i * 8) * 128 + c4B) * 4u;
        }
    }

    float2 acc[4][8];
#pragma unroll
    for (int i = 0; i < 4; i++)
#pragma unroll
        for (int j = 0; j < 8; j++) acc[i][j] = make_float2(0.f, 0.f);

    float4 ra[2];
#pragma unroll
    for (int i = 0; i < 2; i++) cp_async16(sBdst[0][i], bSrc[i]);
    cp_commit();
#pragma unroll
    for (int i = 0; i < 2; i++) ra[i] = *(const float4*)(aSrc[i]);
#pragma unroll
    for (int i = 0; i < 2; i++) {
        sA[0][kqA + 0][aRowLocal[i]] = ra[i].x;
        sA[0][kqA + 1][aRowLocal[i]] = ra[i].y;
        sA[0][kqA + 2][aRowLocal[i]] = ra[i].z;
        sA[0][kqA + 3][aRowLocal[i]] = ra[i].w;
    }
    cp_wait0();
    __syncthreads();

    const int NKC = 256 / 16;
    for (int it = 0; it < NKC; it++) {
        int buf = it & 1;
        if (it + 1 < NKC) {
            int kc = (it + 1) * 16;
            int nb = buf ^ 1;
#pragma unroll
            for (int i = 0; i < 2; i++)
                cp_async16(sBdst[nb][i], bSrc[i] + (size_t)kc * G3);
            cp_commit();
#pragma unroll
            for (int i = 0; i < 2; i++) ra[i] = *(const float4*)(aSrc[i] + kc);
        }
#pragma unroll
        for (int kk = 0; kk < 16; kk++) {
            float2 ar[4];
            ar[0] = *(const float2*)&sA[buf][kk][ty * 4 + 0];
            ar[1] = *(const float2*)&sA[buf][kk][ty * 4 + 2];
            ar[2] = *(const float2*)&sA[buf][kk][64 + ty * 4 + 0];
            ar[3] = *(const float2*)&sA[buf][kk][64 + ty * 4 + 2];
            float4 b0 = *(const float4*)&sB[buf][kk][tx * 4];
            float4 b1 = *(const float4*)&sB[buf][kk][64 + tx * 4];
            float bs[8] = {b0.x, b0.y, b0.z, b0.w, b1.x, b1.y, b1.z, b1.w};
#pragma unroll
            for (int c = 0; c < 8; c++) {
                float2 bb = make_float2(bs[c], bs[c]);
#pragma unroll
                for (int rp = 0; rp < 4; rp++) ffma2(acc[rp][c], ar[rp], bb);
            }
        }
        if (it + 1 < NKC) {
            int nb = buf ^ 1;
#pragma unroll
            for (int i = 0; i < 2; i++) {
                sA[nb][kqA + 0][aRowLocal[i]] = ra[i].x;
                sA[nb][kqA + 1][aRowLocal[i]] = ra[i].y;
                sA[nb][kqA + 2][aRowLocal[i]] = ra[i].z;
                sA[nb][kqA + 3][aRowLocal[i]] = ra[i].w;
            }
            cp_wait0();
        }
        __syncthreads();
    }

    float* Pd = P + (size_t)d * PSTR;
    float4 bcl = *(const float4*)&bih[d * G3 + c0 + tx * 4];
    float4 bch = *(const float4*)&bih[d * G3 + c0 + 64 + tx * 4];
#pragma unroll
    for (int rp = 0; rp < 4; rp++) {
        int row = m0 + ((rp >> 1) << 6) + ty * 4 + ((rp & 1) << 1);
        float4 v;
        v = make_float4(acc[rp][0].x + bcl.x, acc[rp][1].x + bcl.y,
                        acc[rp][2].x + bcl.z, acc[rp][3].x + bcl.w);
        *(float4*)&Pd[(size_t)row * G3 + c0 + tx * 4] = v;
        v = make_float4(acc[rp][0].y + bcl.x, acc[rp][1].y + bcl.y,
                        acc[rp][2].y + bcl.z, acc[rp][3].y + bcl.w);
        *(float4*)&Pd[(size_t)(row + 1) * G3 + c0 + tx * 4] = v;
        v = make_float4(acc[rp][4].x + bch.x, acc[rp][5].x + bch.y,
                        acc[rp][6].x + bch.z, acc[rp][7].x + bch.w);
        *(float4*)&Pd[(size_t)row * G3 + c0 + 64 + tx * 4] = v;
        v = make_float4(acc[rp][4].y + bch.x, acc[rp][5].y + bch.y,
                        acc[rp][6].y + bch.z, acc[rp][7].y + bch.w);
        *(float4*)&Pd[(size_t)(row + 1) * G3 + c0 + 64 + tx * 4] = v;
    }
}

// ---------------- input-projection GEMM (dense; sentence/review levels) ----------------
__global__ __launch_bounds__(256, 2) void gemm_in_k(
    const float* __restrict__ A, const float* __restrict__ WT,
    const float* __restrict__ bih, float* __restrict__ G, int N, int T)
{
    __shared__ float sA[2][16][130];
    __shared__ float sB[2][16][128];
    int d  = blockIdx.z;
    int m0 = blockIdx.x * 128;
    int c0 = blockIdx.y * 128;
    int tid = threadIdx.x;
    int tx = tid & 15, ty = tid >> 4;
    const float* WTd = WT + (size_t)d * 256 * G3;

    int aRowLocal[2];
    const float* aSrc[2];
    int kqA = (tid & 3) << 2;
#pragma unroll
    for (int i = 0; i < 2; i++) {
        int row = i * 64 + (tid >> 2);
        aRowLocal[i] = row;
        int m = m0 + row;
        int t = m / N;
        int n = m - t * N;
        int tt = d ? (T - 1 - t) : t;
        aSrc[i] = A + (size_t)(n * T + tt) * 256 + kqA;
    }
    int kkB = tid >> 5;
    int c4B = (tid & 31) << 2;
    const float* bSrc[2];
    uint32_t sBdst[2][2];
    {
        uint32_t sBbase = (uint32_t)__cvta_generic_to_shared(&sB[0][0][0]);
#pragma unroll
        for (int i = 0; i < 2; i++) {
            bSrc[i] = WTd + (size_t)(kkB + i * 8) * G3 + c0 + c4B;
#pragma unroll
            for (int b = 0; b < 2; b++)
                sBdst[b][i] = sBbase + (uint32_t)(b * 16 * 128 + (kkB + i * 8) * 128 + c4B) * 4u;
        }
    }

    float2 acc[4][8];
#pragma unroll
    for (int i = 0; i < 4; i++)
#pragma unroll
        for (int j = 0; j < 8; j++) acc[i][j] = make_float2(0.f, 0.f);

    float4 ra[2];
#pragma unroll
    for (int i = 0; i < 2; i++) cp_async16(sBdst[0][i], bSrc[i]);
    cp_commit();
#pragma unroll
    for (int i = 0; i < 2; i++) ra[i] = *(const float4*)(aSrc[i]);
#pragma unroll
    for (int i = 0; i < 2; i++) {
        sA[0][kqA + 0][aRowLocal[i]] = ra[i].x;
        sA[0][kqA + 1][aRowLocal[i]] = ra[i].y;
        sA[0][kqA + 2][aRowLocal[i]] = ra[i].z;
        sA[0][kqA + 3][aRowLocal[i]] = ra[i].w;
    }
    cp_wait0();
    __syncthreads();

    const int NKC = 256 / 16;
    for (int it = 0; it < NKC; it++) {
        int buf = it & 1;
        if (it + 1 < NKC) {
            int kc = (it + 1) * 16;
            int nb = buf ^ 1;
#pragma unroll
            for (int i = 0; i < 2; i++)
                cp_async16(sBdst[nb][i], bSrc[i] + (size_t)kc * G3);
            cp_commit();
#pragma unroll
            for (int i = 0; i < 2; i++) ra[i] = *(const float4*)(aSrc[i] + kc);
        }
#pragma unroll
        for (int kk = 0; kk < 16; kk++) {
            float2 ar[4];
            ar[0] = *(const float2*)&sA[buf][kk][ty * 4 + 0];
            ar[1] = *(const float2*)&sA[buf][kk][ty * 4 + 2];
            ar[2] = *(const float2*)&sA[buf][kk][64 + ty * 4 + 0];
            ar[3] = *(const float2*)&sA[buf][kk][64 + ty * 4 + 2];
            float4 b0 = *(const float4*)&sB[buf][kk][tx * 4];
            float4 b1 = *(const float4*)&sB[buf][kk][64 + tx * 4];
            float bs[8] = {b0.x, b0.y, b0.z, b0.w, b1.x, b1.y, b1.z, b1.w};
#pragma unroll
            for (int c = 0; c < 8; c++) {
                float2 bb = make_float2(bs[c], bs[c]);
#pragma unroll
                for (int rp = 0; rp < 4; rp++) ffma2(acc[rp][c], ar[rp], bb);
            }
        }
        if (it + 1 < NKC) {
            int nb = buf ^ 1;
#pragma unroll
            for (int i = 0; i < 2; i++) {
                sA[nb][kqA + 0][aRowLocal[i]] = ra[i].x;
                sA[nb][kqA + 1][aRowLocal[i]] = ra[i].y;
                sA[nb][kqA + 2][aRowLocal[i]] = ra[i].z;
                sA[nb][kqA + 3][aRowLocal[i]] = ra[i].w;
            }
            cp_wait0();
        }
        __syncthreads();
    }

    float* Gd = G + (size_t)d * N * T * G3;
    float4 bcl = *(const float4*)&bih[d * G3 + c0 + tx * 4];
    float4 bch = *(const float4*)&bih[d * G3 + c0 + 64 + tx * 4];
#pragma unroll
    for (int rp = 0; rp < 4; rp++) {
        int row = m0 + ((rp >> 1) << 6) + ty * 4 + ((rp & 1) << 1);
        float4 v;
        v = make_float4(acc[rp][0].x + bcl.x, acc[rp][1].x + bcl.y,
                        acc[rp][2].x + bcl.z, acc[rp][3].x + bcl.w);
        *(float4*)&Gd[(size_t)row * G3 + c0 + tx * 4] = v;
        v = make_float4(acc[rp][0].y + bcl.x, acc[rp][1].y + bcl.y,
                        acc[rp][2].y + bcl.z, acc[rp][3].y + bcl.w);
        *(float4*)&Gd[(size_t)(row + 1) * G3 + c0 + tx * 4] = v;
        v = make_float4(acc[rp][4].x + bch.x, acc[rp][5].x + bch.y,
                        acc[rp][6].x + bch.z, acc[rp][7].x + bch.w);
        *(float4*)&Gd[(size_t)row * G3 + c0 + 64 + tx * 4] = v;
        v = make_float4(acc[rp][4].y + bch.x, acc[rp][5].y + bch.y,
                        acc[rp][6].y + bch.z, acc[rp][7].y + bch.w);
        *(float4*)&Gd[(size_t)(row + 1) * G3 + c0 + 64 + tx * 4] = v;
    }
}

// ---------------- GRU step 0 ----------------
__global__ void gru_step0_k(float* __restrict__ hn, const float* __restrict__ bhh,
                            const float* __restrict__ Gt, size_t dG, int N,
                            const int* __restrict__ tok32, int T)
{
    int i = blockIdx.x * 256 + threadIdx.x;
    int total = 2 * N * 256;
    if (i >= total) return;
    int d = i / (N * 256);
    int rem = i - d * (N * 256);
    int n = rem >> 8;
    int j = rem & 255;
    const float* Gd = Gt + (size_t)d * dG;
    const float* bh = bhh + d * G3;
    size_t gb;
    if (tok32) {
        int tt = d ? (T - 1) : 0;
        int tv = tok32[n * T + tt];
        gb = (size_t)tv * G3 + j;
    } else {
        gb = (size_t)n * G3 + j;
    }
    float r  = fsigmoid(Gd[gb] + bh[j]);
    float z  = fsigmoid(Gd[gb + 256] + bh[256 + j]);
    float nn = ftanh(Gd[gb + 512] + r * bh[512 + j]);
    hn[(size_t)d * HSTR + (size_t)n * 256 + j] = (1.f - z) * nn;
}

// ---------------- word-level GRU step: 4n x 4j tiling, vectorized LDS ----------------
// Grid (32, 4, 2). Bit-identical accumulation order vs previous (k ascending).
__global__ __launch_bounds__(256, 2) void gru_stepw_k(
    const float* __restrict__ hp, float* __restrict__ hn,
    const float* __restrict__ WhhT, const float* __restrict__ bhh,
    const float* __restrict__ Gt, size_t dG,
    const int* __restrict__ tok32, int t, int T)
{
    __shared__ float sH[2][16][68];      // [k][n], stride 68 for 16B-aligned rows
    __shared__ float sW[2][16 * 192];    // [k][g][j]
    int d  = blockIdx.z;
    int n0 = blockIdx.x * 64;
    int j0 = blockIdx.y * 64;
    int tid = threadIdx.x;
    int tx = tid & 15, ty = tid >> 4;    // tx: 4 j each; ty: 4 n each
    const float* hpd = hp + (size_t)d * HSTR;
    const float* Wd  = WhhT + (size_t)d * 256 * G3;

    // h tile: one float4 per thread (4 k of one n row)
    int hRow = tid >> 2;                 // 0..63
    int hKq  = (tid & 3) << 2;
    const float* hSrc = hpd + (size_t)(n0 + hRow) * 256 + hKq;
    // W tile via cp.async: 768 float4s, 3 per thread
    const float* wSrc[3];
    uint32_t wDstB[2][3];
    {
        uint32_t sWbase = (uint32_t)__cvta_generic_to_shared(&sW[0][0]);
#pragma unroll
        for (int i = 0; i < 3; i++) {
            int idx = i * 256 + tid;     // 0..767
            int kk = idx / 48;           // 48 float4 per k-slice
            int r = idx - kk * 48;
            int g = r >> 4;              // 16 float4 per gate
            int j4 = (r & 15) << 2;
            wSrc[i] = Wd + (size_t)kk * G3 + g * 256 + j0 + j4;
            int fofs = kk * 192 + g * 64 + j4;
#pragma unroll
            for (int b = 0; b < 2; b++)
                wDstB[b][i] = sWbase + (uint32_t)(b * 16 * 192 + fofs) * 4u;
        }
    }

    float2 acc[2][3][4];                 // [n-pair][gate][j]
#pragma unroll
    for (int a = 0; a < 2; a++)
#pragma unroll
        for (int g = 0; g < 3; g++)
#pragma unroll
            for (int j = 0; j < 4; j++) acc[a][g][j] = make_float2(0.f, 0.f);

    // Prologue
    float4 rh;
#pragma unroll
    for (int i = 0; i < 3; i++) cp_async16(wDstB[0][i], wSrc[i]);
    cp_commit();
    rh = *(const float4*)(hSrc);
    sH[0][hKq + 0][hRow] = rh.x; sH[0][hKq + 1][hRow] = rh.y;
    sH[0][hKq + 2][hRow] = rh.z; sH[0][hKq + 3][hRow] = rh.w;
    cp_wait0();
    __syncthreads();

    for (int it = 0; it < 16; it++) {
        int buf = it & 1;
        if (it + 1 < 16) {
            int kc = (it + 1) * 16;
            int nb = buf ^ 1;
#pragma unroll
            for (int i = 0; i < 3; i++)
                cp_async16(wDstB[nb][i], wSrc[i] + (size_t)kc * G3);
            cp_commit();
            rh = *(const float4*)(hSrc + kc);
        }
#pragma unroll
        for (int kk = 0; kk < 16; kk++) {
            float4 av = *(const float4*)&sH[buf][kk][ty * 4];
            float2 a01 = make_float2(av.x, av.y);
            float2 a23 = make_float2(av.z, av.w);
#pragma unroll
            for (int g = 0; g < 3; g++) {
                float4 w = *(const float4*)&sW[buf][kk * 192 + g * 64 + tx * 4];
                float ws[4] = {w.x, w.y, w.z, w.w};
#pragma unroll
                for (int j = 0; j < 4; j++) {
                    float2 bb = make_float2(ws[j], ws[j]);
                    ffma2(acc[0][g][j], a01, bb);
                    ffma2(acc[1][g][j], a23, bb);
                }
            }
        }
        if (it + 1 < 16) {
            int nb = buf ^ 1;
            sH[nb][hKq + 0][hRow] = rh.x; sH[nb][hKq + 1][hRow] = rh.y;
            sH[nb][hKq + 2][hRow] = rh.z; sH[nb][hKq + 3][hRow] = rh.w;
            cp_wait0();
        }
        __syncthreads();
    }

    const float* Gd = Gt + (size_t)d * dG;
    const float* bh = bhh + d * G3;
    float* hnd = hn + (size_t)d * HSTR;
    int jb = j0 + tx * 4;
    int tt = d ? (T - 1 - t) : t;
    float4 b0v = *(const float4*)&bh[jb];
    float4 b1v = *(const float4*)&bh[256 + jb];
    float4 b2v = *(const float4*)&bh[512 + jb];
    float bs0[4] = {b0v.x, b0v.y, b0v.z, b0v.w};
    float bs1[4] = {b1v.x, b1v.y, b1v.z, b1v.w};
    float bs2[4] = {b2v.x, b2v.y, b2v.z, b2v.w};
#pragma unroll
    for (int nn = 0; nn < 4; nn++) {
        int n = n0 + ty * 4 + nn;
        int np = nn >> 1;
        bool hi = nn & 1;
        int tv = tok32[n * T + tt];
        size_t gb = (size_t)tv * G3 + jb;
        float4 G0 = *(const float4*)&Gd[gb];
        float4 G1 = *(const float4*)&Gd[gb + 256];
        float4 G2 = *(const float4*)&Gd[gb + 512];
        float4 hp4 = *(const float4*)&hpd[(size_t)n * 256 + jb];
        float gs0[4] = {G0.x, G0.y, G0.z, G0.w};
        float gs1[4] = {G1.x, G1.y, G1.z, G1.w};
        float gs2[4] = {G2.x, G2.y, G2.z, G2.w};
        float hs[4]  = {hp4.x, hp4.y, hp4.z, hp4.w};
        float res[4];
#pragma unroll
        for (int j = 0; j < 4; j++) {
            float a0 = hi ? acc[np][0][j].y : acc[np][0][j].x;
            float a1 = hi ? acc[np][1][j].y : acc[np][1][j].x;
            float a2 = hi ? acc[np][2][j].y : acc[np][2][j].x;
            float r  = fsigmoid(gs0[j] + a0 + bs0[j]);
            float z  = fsigmoid(gs1[j] + a1 + bs1[j]);
            float nv = ftanh(gs2[j] + r * (a2 + bs2[j]));
            res[j] = (1.f - z) * nv + z * hs[j];
        }
        *(float4*)&hnd[(size_t)n * 256 + jb] =
            make_float4(res[0], res[1], res[2], res[3]);
    }
}

// ---------------- fused GRU recurrent step (sentence/review levels) ----------------
template<int JT, bool TOK>
__global__ __launch_bounds__(256, 2) void gru_step_k(
    const float* __restrict__ hp, float* __restrict__ hn,
    const float* __restrict__ WhhT, const float* __restrict__ bhh,
    const float* __restrict__ Gt, size_t dG, int N,
    const int* __restrict__ tok32, int t, int T)
{
    __shared__ float sH[2][16][66];
    __shared__ float sW[2][16 * 3 * JT];
    int d  = blockIdx.z;
    int n0 = blockIdx.x * 64;
    int j0 = blockIdx.y * JT;
    int tid = threadIdx.x;
    const int TXN = JT / 2;
    const int TYN = 256 / TXN;
    const int NPT = 64 / TYN;
    int tx = tid % TXN, ty = tid / TXN;
    const float* hpd = hp + (size_t)d * HSTR;
    const float* Wd  = WhhT + (size_t)d * 256 * G3;

    int hRow = tid >> 2;
    int hKq  = (tid & 3) << 2;
    bool hValid = (n0 + hRow) < N;
    const float* hSrc = hpd + (size_t)(hValid ? (n0 + hRow) : 0) * 256 + hKq;
    const int NF4 = 16 * 3 * JT / 4;
    const int NP4 = (NF4 + 255) / 256;
    const float* wSrc[NP4];
    uint32_t wDstB[2][NP4];
    bool wAct[NP4];
    {
        uint32_t sWbase = (uint32_t)__cvta_generic_to_shared(&sW[0][0]);
#pragma unroll
        for (int i = 0; i < NP4; i++) {
            int idx = i * 256 + tid;
            wAct[i] = idx < NF4;
            int perk = 3 * JT / 4;
            int ii = wAct[i] ? idx : 0;
            int kk = ii / perk;
            int r = ii - kk * perk;
            int g = r / (JT / 4);
            int j4 = (r - g * (JT / 4)) << 2;
            wSrc[i] = Wd + (size_t)kk * G3 + g * 256 + j0 + j4;
            int fofs = kk * (3 * JT) + g * JT + j4;
#pragma unroll
            for (int b = 0; b < 2; b++)
                wDstB[b][i] = sWbase + (uint32_t)(b * 16 * 3 * JT + fofs) * 4u;
        }
    }

    float2 acc[NPT/2][3][2];
#pragma unroll
    for (int a = 0; a < NPT/2; a++)
#pragma unroll
        for (int g = 0; g < 3; g++)
#pragma unroll
            for (int jj = 0; jj < 2; jj++) acc[a][g][jj] = make_float2(0.f, 0.f);

    float4 rh;
#pragma unroll
    for (int i = 0; i < NP4; i++)
        if (wAct[i]) cp_async16(wDstB[0][i], wSrc[i]);
    cp_commit();
    rh = hValid ? *(const float4*)(hSrc) : make_float4(0.f, 0.f, 0.f, 0.f);
    sH[0][hKq + 0][hRow] = rh.x; sH[0][hKq + 1][hRow] = rh.y;
    sH[0][hKq + 2][hRow] = rh.z; sH[0][hKq + 3][hRow] = rh.w;
    cp_wait0();
    __syncthreads();

    const int NKC = 256 / 16;
    for (int it = 0; it < NKC; it++) {
        int buf = it & 1;
        if (it + 1 < NKC) {
            int kc = (it + 1) * 16;
            int nb = buf ^ 1;
#pragma unroll
            for (int i = 0; i < NP4; i++)
                if (wAct[i]) cp_async16(wDstB[nb][i], wSrc[i] + (size_t)kc * G3);
            cp_commit();
            rh = hValid ? *(const float4*)(hSrc + kc) : make_float4(0.f, 0.f, 0.f, 0.f);
        }
#pragma unroll
        for (int kk = 0; kk < 16; kk++) {
            float2 ar[NPT/2];
#pragma unroll
            for (int rp = 0; rp < NPT/2; rp++)
                ar[rp] = *(const float2*)&sH[buf][kk][ty * NPT + rp * 2];
#pragma unroll
            for (int g = 0; g < 3; g++) {
                float2 w = *(const float2*)&sW[buf][kk * (3 * JT) + g * JT + tx * 2];
                float2 b0 = make_float2(w.x, w.x);
                float2 b1 = make_float2(w.y, w.y);
#pragma unroll
                for (int rp = 0; rp < NPT/2; rp++) {
                    ffma2(acc[rp][g][0], ar[rp], b0);
                    ffma2(acc[rp][g][1], ar[rp], b1);
                }
            }
        }
        if (it + 1 < NKC) {
            int nb = buf ^ 1;
            sH[nb][hKq + 0][hRow] = rh.x; sH[nb][hKq + 1][hRow] = rh.y;
            sH[nb][hKq + 2][hRow] = rh.z; sH[nb][hKq + 3][hRow] = rh.w;
            cp_wait0();
        }
        __syncthreads();
    }

    const float* Gd = Gt + (size_t)d * dG;
    const float* bh = bhh + d * G3;
    float* hnd = hn + (size_t)d * HSTR;
    int jb = j0 + tx * 2;
    int tt = d ? (T - 1 - t) : t;
    float2 bh0 = *(const float2*)&bh[jb];
    float2 bh1 = *(const float2*)&bh[256 + jb];
    float2 bh2 = *(const float2*)&bh[512 + jb];
#pragma unroll
    for (int rp = 0; rp < NPT/2; rp++) {
#pragma unroll
        for (int lane = 0; lane < 2; lane++) {
            int n = n0 + ty * NPT + rp * 2 + lane;
            if (n >= N) continue;
            size_t gb;
            if (TOK) {
                int tv = tok32[n * T + tt];
                gb = (size_t)tv * G3 + jb;
            } else {
                gb = (size_t)n * G3 + jb;
            }
            float2 G0 = *(const float2*)&Gd[gb];
            float2 G1 = *(const float2*)&Gd[gb + 256];
            float2 G2 = *(const float2*)&Gd[gb + 512];
            float2 hp2 = *(const float2*)&hpd[(size_t)n * 256 + jb];
            float2 res;
#pragma unroll
            for (int jj = 0; jj < 2; jj++) {
                float a0 = lane ? acc[rp][0][jj].y : acc[rp][0][jj].x;
                float a1 = lane ? acc[rp][1][jj].y : acc[rp][1][jj].x;
                float a2 = lane ? acc[rp][2][jj].y : acc[rp][2][jj].x;
                float gx0 = jj ? G0.y : G0.x, gx1 = jj ? G1.y : G1.x, gx2 = jj ? G2.y : G2.x;
                float bb0 = jj ? bh0.y : bh0.x, bb1 = jj ? bh1.y : bh1.x, bb2 = jj ? bh2.y : bh2.x;
                float hpv = jj ? hp2.y : hp2.x;
                float r  = fsigmoid(gx0 + a0 + bb0);
                float z  = fsigmoid(gx1 + a1 + bb1);
                float nn = ftanh(gx2 + r * (a2 + bb2));
                float o  = (1.f - z) * nn + z * hpv;
                if (jj) res.y = o; else res.x = o;
            }
            *(float2*)&hnd[(size_t)n * 256 + jb] = res;
        }
    }
}

// ---------------- FC head: Linear(256->128) -> SELU -> Linear(128->1) ----------------
__global__ void fc_head_k(const float* __restrict__ in, const float* __restrict__ W1,
                          const float* __restrict__ b1, const float* __restrict__ W2,
                          const float* __restrict__ b2, float* __restrict__ out)
{
    __shared__ float red[128];
    int row = blockIdx.x, j = threadIdx.x;
    const float* x = in + (size_t)row * 256;
    const float* w = W1 + (size_t)j * 256;
    float s = b1[j];
#pragma unroll 4
    for (int k = 0; k < 256; k += 4) {
        float4 xv = *(const float4*)&x[k];
        float4 wv = *(const float4*)&w[k];
        s += xv.x * wv.x + xv.y * wv.y + xv.z * wv.z + xv.w * wv.w;
    }
    const float SC = 1.0507009873554805f, AL = 1.6732632423543772f;
    float v = s > 0.f ? SC * s : SC * AL * (expf(s) - 1.f);
    red[j] = v * W2[j];
    __syncthreads();
    for (int o = 64; o > 0; o >>= 1) {
        if (j < o) red[j] += red[j + o];
        __syncthreads();
    }
    if (j == 0) out[row] = red[0] + b2[0];
}

// ---------------- orchestration ----------------
extern "C" void kernel_launch(void* const* d_in, const int* in_sizes, int n_in,
                              void* d_out, int out_size)
{
    const void*  tok   = d_in[0];
    const float* emb   = (const float*)d_in[1];
    const float* wWih  = (const float*)d_in[2];
    const float* wWhh  = (const float*)d_in[3];
    const float* wbih  = (const float*)d_in[4];
    const float* wbhh  = (const float*)d_in[5];
    const float* sWih  = (const float*)d_in[6];
    const float* sWhh  = (const float*)d_in[7];
    const float* sbih  = (const float*)d_in[8];
    const float* sbhh  = (const float*)d_in[9];
    const float* rWih  = (const float*)d_in[10];
    const float* rWhh  = (const float*)d_in[11];
    const float* rbih  = (const float*)d_in[12];
    const float* rbhh  = (const float*)d_in[13];
    const float* rfcW1 = (const float*)d_in[14];
    const float* rfcb1 = (const float*)d_in[15];
    const float* rfcW2 = (const float*)d_in[16];
    const float* rfcb2 = (const float*)d_in[17];
    const float* pfcW1 = (const float*)d_in[18];
    const float* pfcb1 = (const float*)d_in[19];
    const float* pfcW2 = (const float*)d_in[20];
    const float* pfcb2 = (const float*)d_in[21];
    float* out = (float*)d_out;

    dim3 tb(32, 8);
    float *pWihT_w, *pWhhT_w, *pWihT_s, *pWhhT_s, *pWihT_r, *pWhhT_r;
    float *pP, *pGs, *pGr, *pHA, *pHB, *pSent, *pRev, *pBiz;
    int *pTok32;
    cudaGetSymbolAddress((void**)&pWihT_w, g_WihT_w);
    cudaGetSymbolAddress((void**)&pWhhT_w, g_WhhT_w);
    cudaGetSymbolAddress((void**)&pWihT_s, g_WihT_s);
    cudaGetSymbolAddress((void**)&pWhhT_s, g_WhhT_s);
    cudaGetSymbolAddress((void**)&pWihT_r, g_WihT_r);
    cudaGetSymbolAddress((void**)&pWhhT_r, g_WhhT_r);
    cudaGetSymbolAddress((void**)&pP,   g_P);
    cudaGetSymbolAddress((void**)&pGs,  g_Gs);
    cudaGetSymbolAddress((void**)&pGr,  g_Gr);
    cudaGetSymbolAddress((void**)&pHA,  g_hA);
    cudaGetSymbolAddress((void**)&pHB,  g_hB);
    cudaGetSymbolAddress((void**)&pSent, g_sent);
    cudaGetSymbolAddress((void**)&pRev,  g_rev);
    cudaGetSymbolAddress((void**)&pBiz,  g_biz);
    cudaGetSymbolAddress((void**)&pTok32, g_tok32);

    transpose6_k<<<dim3(24, 8, 12), tb>>>(
        wWih, wWhh, sWih, sWhh, rWih, rWhh,
        pWihT_w, pWhhT_w, pWihT_s, pWhhT_s, pWihT_r, pWhhT_r);

    detect_k<<<1, 32>>>((const int*)tok);
    tok32_k<<<(NW * TW + 255) / 256, 256>>>(tok);

    // ---- word level: project vocab table once, gather per step ----
    gemm_emb_k<<<dim3(PROWS / 128, 6, 2), 256>>>(emb, pWihT_w, wbih, pP);
    {
        float* ha = pHA; float* hb = pHB;
        gru_step0_k<<<(2 * NW * 256 + 255) / 256, 256>>>(hb, wbhh,
            pP, PSTR, NW, pTok32, TW);
        { float* tmp = ha; ha = hb; hb = tmp; }
        for (int t = 1; t < TW; t++) {
            gru_stepw_k<<<dim3(32, 4, 2), 256>>>(ha, hb, pWhhT_w, wbhh,
                pP, PSTR, pTok32, t, TW);
            float* tmp = ha; ha = hb; hb = tmp;
        }
        add_dirs_k<<<2048, 256>>>(ha, pSent, NW * HH);
    }

    // ---- sentence level ----
    gemm_in_k<<<dim3(16, 6, 2), 256>>>(pSent, pWihT_s, sbih, pGs, NS, TS);
    {
        float* ha = pHA; float* hb = pHB;
        gru_step0_k<<<(2 * NS * 256 + 255) / 256, 256>>>(hb, sbhh,
            pGs, (size_t)TS * NS * G3, NS, nullptr, 0);
        { float* tmp = ha; ha = hb; hb = tmp; }
        for (int t = 1; t < TS; t++) {
            gru_step_k<32, false><<<dim3(2, 8, 2), 256>>>(ha, hb, pWhhT_s, sbhh,
                pGs + (size_t)t * NS * G3, (size_t)TS * NS * G3, NS, nullptr, 0, 0);
            float* tmp = ha; ha = hb; hb = tmp;
        }
        add_dirs_k<<<128, 256>>>(ha, pRev, NS * HH);
    }

    fc_head_k<<<128, 128>>>(pRev, rfcW1, rfcb1, rfcW2, rfcb2, out + 8);

    // ---- review level ----
    gemm_in_k<<<dim3(1, 6, 2), 256>>>(pRev, pWihT_r, rbih, pGr, NR, TR);
    {
        float* ha = pHA; float* hb = pHB;
        gru_step0_k<<<(2 * NR * 256 + 255) / 256, 256>>>(hb, rbhh,
            pGr, (size_t)TR * NR * G3, NR, nullptr, 0);
        { float* tmp = ha; ha = hb; hb = tmp; }
        for (int t = 1; t < TR; t++) {
            gru_step_k<32, false><<<dim3(1, 8, 2), 256>>>(ha, hb, pWhhT_r, rbhh,
                pGr + (size_t)t * NR * G3, (size_t)TR * NR * G3, NR, nullptr, 0, 0);
            float* tmp = ha; ha = hb; hb = tmp;
        }
        add_dirs_k<<<8, 256>>>(ha, pBiz, NR * HH);
    }

    fc_head_k<<<8, 128>>>(pBiz, pfcW1, pfcb1, pfcW2, pfcb2, out);
}